// round 6
// baseline (speedup 1.0000x reference)
#include <cuda_runtime.h>
#include <math.h>

#define NB     32768
#define N_INTR 32
#define OWN_D  3
#define INT_D  7
#define AD     128
#define HID    256
#define OUT_D  2
#define OBS_D  227
#define SPB    32      // samples per block (attn kernel)
#define SB     32      // samples per block (mlp kernel)
#define NEG    0.2f

// scratch: concat(own_e, attn_vec) -> [NB, 256]
__device__ float g_x[NB * 2 * AD];

__device__ __forceinline__ float lrelu(float x) { return x > 0.f ? x : NEG * x; }

extern __shared__ float sm[];

// ---------------------------------------------------------------------------
// Kernel A: embeddings + additive attention + proj. One CTA = 32 samples.
// Thread j in [0,128) owns output column j of every 128-wide vector.
// ---------------------------------------------------------------------------
__global__ __launch_bounds__(128, 1)
void attn_kernel(const float* __restrict__ obs,
                 const float* __restrict__ own_W, const float* __restrict__ own_b,
                 const float* __restrict__ int_W, const float* __restrict__ int_b,
                 const float* __restrict__ Wq, const float* __restrict__ Wk,
                 const float* __restrict__ Wv, const float* __restrict__ v_att,
                 const float* __restrict__ proj_W, const float* __restrict__ proj_b)
{
    float* sWk   = sm;                   // 128*128
    float* sWv   = sWk + AD * AD;        // 128*128
    float* sIE   = sWv + AD * AD;        // 32*128  (int_e for current sample)
    float* sOwnE = sIE + N_INTR * AD;    // 32*128
    float* sQ    = sOwnE + SPB * AD;     // 32*128
    float* sCtx  = sQ + SPB * AD;        // 32*128
    float* sPart = sCtx + SPB * AD;      // 32*129  (score partials, padded)
    float* sObs  = sPart + N_INTR * 129; // 228
    float* sOwnW = sObs + 228;           // 3*128
    float* sIntW = sOwnW + 3 * AD;       // 7*128
    float* sOwnB = sIntW + 7 * AD;       // 128
    float* sIntB = sOwnB + AD;           // 128
    float* sVatt = sIntB + AD;           // 128
    float* sAlpha = sVatt + AD;          // 32
    float* sPad   = sAlpha + N_INTR;     // 32

    const int j  = threadIdx.x;
    const int s0 = blockIdx.x * SPB;

    // stage weights
    for (int i = j; i < AD * AD; i += 128) { sWk[i] = Wk[i]; sWv[i] = Wv[i]; }
    for (int i = j; i < 3 * AD; i += 128) sOwnW[i] = own_W[i];
    for (int i = j; i < 7 * AD; i += 128) sIntW[i] = int_W[i];
    sOwnB[j] = own_b[j];
    sIntB[j] = int_b[j];
    sVatt[j] = v_att[j];
    __syncthreads();

    // Phase A: own_e for all samples of this block
    for (int s = 0; s < SPB; ++s) {
        const float* o = obs + (s0 + s) * OBS_D;
        float acc = sOwnB[j]
                  + o[0] * sOwnW[0 * AD + j]
                  + o[1] * sOwnW[1 * AD + j]
                  + o[2] * sOwnW[2 * AD + j];
        float oe = lrelu(acc);
        sOwnE[s * AD + j] = oe;
        g_x[(s0 + s) * (2 * AD) + j] = oe;   // first half of concat output
    }
    __syncthreads();

    // Phase B: q[s][j] = sum_d own_e[s][d] * Wq[d][j]  (Wq from L2, reused x32)
    {
        float acc[SPB];
        #pragma unroll
        for (int s = 0; s < SPB; ++s) acc[s] = 0.f;
        for (int d = 0; d < AD; ++d) {
            float wq = Wq[d * AD + j];
            #pragma unroll
            for (int s = 0; s < SPB; ++s) acc[s] = fmaf(sOwnE[s * AD + d], wq, acc[s]);
        }
        #pragma unroll
        for (int s = 0; s < SPB; ++s) sQ[s * AD + j] = acc[s];
    }
    __syncthreads();

    // Phase C: per-sample attention mainloop
    for (int s = 0; s < SPB; ++s) {
        const float* o = obs + (s0 + s) * OBS_D;
        if (j < 114) {
            sObs[2 * j] = o[2 * j];
            if (2 * j + 1 < OBS_D) sObs[2 * j + 1] = o[2 * j + 1];
        }
        __syncthreads();

        // padding mask (sum |intr| < 1e-6)
        if (j < N_INTR) {
            float asum = 0.f;
            #pragma unroll
            for (int d = 0; d < INT_D; ++d) asum += fabsf(sObs[OWN_D + j * INT_D + d]);
            sPad[j] = (asum < 1e-6f) ? 1.f : 0.f;
        }

        // int_e: thread j fills column j of the 32x128 entity embedding
        #pragma unroll
        for (int n = 0; n < N_INTR; ++n) {
            float acc = sIntB[j];
            #pragma unroll
            for (int d = 0; d < INT_D; ++d)
                acc = fmaf(sObs[OWN_D + n * INT_D + d], sIntW[d * AD + j], acc);
            sIE[n * AD + j] = lrelu(acc);
        }
        __syncthreads();

        // k/v GEMMs: the FLOP hot spot. 64 independent accumulators -> full FFMA ILP.
        float kacc[N_INTR], vacc[N_INTR];
        #pragma unroll
        for (int n = 0; n < N_INTR; ++n) { kacc[n] = 0.f; vacc[n] = 0.f; }
        #pragma unroll 2
        for (int d = 0; d < AD; ++d) {
            float wk = sWk[d * AD + j];
            float wv = sWv[d * AD + j];
            #pragma unroll
            for (int n = 0; n < N_INTR; ++n) {
                float ie = sIE[n * AD + d];   // broadcast load
                kacc[n] = fmaf(ie, wk, kacc[n]);
                vacc[n] = fmaf(ie, wv, vacc[n]);
            }
        }

        // scores: tanh(q + k) @ v_att  -> partials in smem (pad 129 = conflict-free)
        float qv = sQ[s * AD + j];
        float va = sVatt[j];
        #pragma unroll
        for (int n = 0; n < N_INTR; ++n)
            sPart[n * 129 + j] = tanhf(qv + kacc[n]) * va;
        __syncthreads();

        // reduce + masked softmax (warp 0, one lane per entity)
        if (j < N_INTR) {
            float sc = 0.f;
            #pragma unroll 4
            for (int i = 0; i < 128; ++i) sc += sPart[j * 129 + i];
            bool pad = sPad[j] > 0.5f;
            float scm = pad ? -INFINITY : sc;
            float m = scm;
            #pragma unroll
            for (int off = 16; off > 0; off >>= 1)
                m = fmaxf(m, __shfl_xor_sync(0xffffffffu, m, off));
            float e = pad ? 0.f : expf(scm - m);
            float es = e;
            #pragma unroll
            for (int off = 16; off > 0; off >>= 1)
                es += __shfl_xor_sync(0xffffffffu, es, off);
            sAlpha[j] = (es > 0.f) ? (e / es) : 0.f;  // nan_to_num for all-padded rows
        }
        __syncthreads();

        // ctx[j] = sum_n alpha[n] * v[n][j]  (v lives in this thread's registers)
        float ctx = 0.f;
        #pragma unroll
        for (int n = 0; n < N_INTR; ++n) ctx = fmaf(sAlpha[n], vacc[n], ctx);
        sCtx[s * AD + j] = ctx;
        __syncthreads();
    }

    // Phase D: proj for all samples (proj_W from L2, reused x32)
    {
        float acc[SPB];
        float pb = proj_b[j];
        #pragma unroll
        for (int s = 0; s < SPB; ++s) acc[s] = pb;
        for (int d = 0; d < AD; ++d) {
            float pw = proj_W[d * AD + j];
            #pragma unroll
            for (int s = 0; s < SPB; ++s) acc[s] = fmaf(sCtx[s * AD + d], pw, acc[s]);
        }
        #pragma unroll
        for (int s = 0; s < SPB; ++s)
            g_x[(s0 + s) * (2 * AD) + AD + j] = tanhf(acc[s]);  // second half of concat
    }
}

// ---------------------------------------------------------------------------
// Kernel B: MLP head. One CTA = 32 samples, 256 threads (thread j = column j).
// ---------------------------------------------------------------------------
__global__ __launch_bounds__(256)
void mlp_kernel(const float* __restrict__ h1_W, const float* __restrict__ h1_b,
                const float* __restrict__ h2_W, const float* __restrict__ h2_b,
                const float* __restrict__ out_W, const float* __restrict__ out_b,
                float* __restrict__ outp)
{
    float* sX  = sm;                 // 32*256
    float* sH  = sX + SB * HID;      // 32*256
    float* sOW = sH + SB * HID;      // 256*2

    const int j  = threadIdx.x;
    const int s0 = blockIdx.x * SB;

    for (int i = j; i < SB * HID; i += 256) sX[i] = g_x[s0 * HID + i];
    for (int i = j; i < HID * OUT_D; i += 256) sOW[i] = out_W[i];
    __syncthreads();

    float acc[SB];
    // h1
    {
        float b = h1_b[j];
        #pragma unroll
        for (int s = 0; s < SB; ++s) acc[s] = b;
        #pragma unroll 2
        for (int d = 0; d < HID; ++d) {
            float w = h1_W[d * HID + j];
            #pragma unroll
            for (int s = 0; s < SB; ++s) acc[s] = fmaf(sX[s * HID + d], w, acc[s]);
        }
        #pragma unroll
        for (int s = 0; s < SB; ++s) sH[s * HID + j] = lrelu(acc[s]);
    }
    __syncthreads();
    // h2 (writes back into sX)
    {
        float b = h2_b[j];
        #pragma unroll
        for (int s = 0; s < SB; ++s) acc[s] = b;
        #pragma unroll 2
        for (int d = 0; d < HID; ++d) {
            float w = h2_W[d * HID + j];
            #pragma unroll
            for (int s = 0; s < SB; ++s) acc[s] = fmaf(sH[s * HID + d], w, acc[s]);
        }
        #pragma unroll
        for (int s = 0; s < SB; ++s) sX[s * HID + j] = lrelu(acc[s]);
    }
    __syncthreads();
    // out layer: 8 warps x 4 samples, shuffle reduce
    {
        const int w = j >> 5, l = j & 31;
        float b0 = out_b[0], b1 = out_b[1];
        #pragma unroll
        for (int si = 0; si < SB / 8; ++si) {
            int s = w * (SB / 8) + si;
            float p0 = 0.f, p1 = 0.f;
            #pragma unroll
            for (int d = l; d < HID; d += 32) {
                float h = sX[s * HID + d];
                p0 = fmaf(h, sOW[d * 2 + 0], p0);
                p1 = fmaf(h, sOW[d * 2 + 1], p1);
            }
            #pragma unroll
            for (int off = 16; off > 0; off >>= 1) {
                p0 += __shfl_xor_sync(0xffffffffu, p0, off);
                p1 += __shfl_xor_sync(0xffffffffu, p1, off);
            }
            if (l == 0) {
                outp[(s0 + s) * 2 + 0] = p0 + b0;
                outp[(s0 + s) * 2 + 1] = p1 + b1;
            }
        }
    }
}

// ---------------------------------------------------------------------------

extern "C" void kernel_launch(void* const* d_in, const int* in_sizes, int n_in,
                              void* d_out, int out_size)
{
    const float* obs    = (const float*)d_in[0];
    const float* own_W  = (const float*)d_in[1];
    const float* own_b  = (const float*)d_in[2];
    const float* int_W  = (const float*)d_in[3];
    const float* int_b  = (const float*)d_in[4];
    const float* Wq     = (const float*)d_in[5];
    const float* Wk     = (const float*)d_in[6];
    const float* Wv     = (const float*)d_in[7];
    const float* v_att  = (const float*)d_in[8];
    const float* proj_W = (const float*)d_in[9];
    const float* proj_b = (const float*)d_in[10];
    const float* h1_W   = (const float*)d_in[11];
    const float* h1_b   = (const float*)d_in[12];
    const float* h2_W   = (const float*)d_in[13];
    const float* h2_b   = (const float*)d_in[14];
    const float* out_W  = (const float*)d_in[15];
    const float* out_b  = (const float*)d_in[16];

    const size_t smemA = (size_t)(2 * AD * AD        // Wk, Wv
                                + N_INTR * AD        // int_e
                                + 3 * SPB * AD       // own_e, q, ctx
                                + N_INTR * 129       // score partials
                                + 228                // obs row
                                + 3 * AD + 7 * AD    // own_W, int_W
                                + 3 * AD             // own_b, int_b, v_att
                                + 2 * N_INTR)        // alpha, pad
                         * sizeof(float);            // = 220,944 B
    const size_t smemB = (size_t)(2 * SB * HID + HID * OUT_D) * sizeof(float); // 67,584 B

    cudaFuncSetAttribute(attn_kernel, cudaFuncAttributeMaxDynamicSharedMemorySize, (int)smemA);
    cudaFuncSetAttribute(mlp_kernel,  cudaFuncAttributeMaxDynamicSharedMemorySize, (int)smemB);

    attn_kernel<<<NB / SPB, 128, smemA>>>(obs, own_W, own_b, int_W, int_b,
                                          Wq, Wk, Wv, v_att, proj_W, proj_b);
    mlp_kernel<<<NB / SB, 256, smemB>>>(h1_W, h1_b, h2_W, h2_b, out_W, out_b,
                                        (float*)d_out);
}